// round 10
// baseline (speedup 1.0000x reference)
#include <cuda_runtime.h>
#include <math_constants.h>
#include <cstdint>

// Problem constants (fixed by dataset: B=2, H=96, W=96, P=32)
#define NTHREADS 256
#define H1S 40    // h1 row stride (floats)  : 40 % 32 == 8  -> LDS.64 conflict-free
#define H2S 264   // h2/C row stride (floats): 264 % 32 == 8 -> LDS.64 conflict-free
#define BPS 520   // B panel g-row stride (floats): 520 % 32 == 8

// Scratch (allocation-free rule: __device__ globals).
// K-paired weights: element [g][n] = (W[n][2g], W[n][2g+1]), tf32-rn rounded.
// The GEMM uses K-permutation (HW slot j <-> storage 2j, j+4 <-> 2j+1) applied
// identically to A and B, which is correctness-neutral and makes every
// fragment pair memory-adjacent (64-bit loads everywhere).
__device__ float g_zfeat[256];
__device__ __align__(16) float g_W2P[16 * 256 * 2];    // 16 g-groups (K=32)
__device__ __align__(16) float g_W3P[128 * 256 * 2];   // 128 g-groups (K=256)

__device__ __forceinline__ float to_tf32_rn(float x) {
    uint32_t r;
    asm("cvt.rna.tf32.f32 %0, %1;" : "=r"(r) : "f"(x));
    return __uint_as_float(r);
}

// ---------------------------------------------------------------------------
// Prep (grid 257 x 256): build K-paired, tf32-rounded W2P/W3P; block 256: zfeat.
// ---------------------------------------------------------------------------
__global__ void prep_kernel(const float* __restrict__ W2,
                            const float* __restrict__ W3,
                            const float* __restrict__ b1,
                            const float* __restrict__ b2,
                            const float* __restrict__ b3) {
    const int t = threadIdx.x;
    const int blk = blockIdx.x;
    if (blk < 256) {
        const int n = blk;
        if (t < 128) {                       // W3 pairs: g = t
            const float2 v = *(const float2*)&W3[n * 256 + t * 2];
            *(float2*)&g_W3P[(t * 256 + n) * 2] =
                make_float2(to_tf32_rn(v.x), to_tf32_rn(v.y));
        } else if (t < 144) {                // W2 pairs: g = t-128 (0..15)
            const int g = t - 128;
            const float2 v = *(const float2*)&W2[n * 32 + g * 2];
            *(float2*)&g_W2P[(g * 256 + n) * 2] =
                make_float2(to_tf32_rn(v.x), to_tf32_rn(v.y));
        }
    } else {
        __shared__ float h1[32];
        __shared__ float h2[256];
        if (t < 32) h1[t] = fmaxf(b1[t], 0.0f);
        __syncthreads();
        float a = b2[t];
#pragma unroll 8
        for (int c = 0; c < 32; c++) a += W2[t * 32 + c] * h1[c];
        h2[t] = fmaxf(a, 0.0f);
        __syncthreads();
        float o = b3[t];
#pragma unroll 8
        for (int c = 0; c < 256; c++) o += W3[t * 256 + c] * h2[c];
        g_zfeat[t] = o;
    }
}

__device__ __forceinline__ void mma_tf32(float* d,
                                         float a0, float a1, float a2, float a3,
                                         float b0, float b1) {
    asm volatile(
        "mma.sync.aligned.m16n8k8.row.col.f32.tf32.tf32.f32 "
        "{%0,%1,%2,%3},{%4,%5,%6,%7},{%8,%9},{%0,%1,%2,%3};"
        : "+f"(d[0]), "+f"(d[1]), "+f"(d[2]), "+f"(d[3])
        : "r"(__float_as_uint(a0)), "r"(__float_as_uint(a1)),
          "r"(__float_as_uint(a2)), "r"(__float_as_uint(a3)),
          "r"(__float_as_uint(b0)), "r"(__float_as_uint(b1)));
}

// ---------------------------------------------------------------------------
// Main: one CTA / 2 voxels; 2 CTAs/SM (111 KB smem, 128 regs).
// Warp tile M=32 (one voxel) x N=64. Both GEMMs 1xTF32-RN via K-paired
// layouts: every A/B fragment load is a single LDS.64, zero in-loop cvt.
// Smem (floats): pts 192 | w1s 96 | b1s 32 | b2s 256 | h1p 64*H1S |
//                h2p 64*H2S (C overlay) | bp 16*BPS
// ---------------------------------------------------------------------------
__global__ void __launch_bounds__(NTHREADS, 2)
voxel_tc_kernel(const float* __restrict__ fv,     // [V][32][3]
                const int*   __restrict__ fvnum,  // [V]
                const float* __restrict__ W1,     // [32][3]
                const float* __restrict__ b1,     // [32]
                const float* __restrict__ b2,     // [256]
                const float* __restrict__ b3,     // [256]
                float* __restrict__ out)          // [V][256]
{
    extern __shared__ float sm[];
    float* pts = sm;                        // 192
    float* w1s = sm + 192;                  // 96
    float* b1s = sm + 288;                  // 32
    float* b2s = sm + 320;                  // 256
    float* h1p = sm + 576;                  // 64*H1S = 2560
    float* h2p = sm + 576 + 64 * H1S;       // 64*H2S = 16896 (later: C)
    float* bp  = sm + 576 + 64 * H1S + 64 * H2S;   // 16*BPS = 8320

    const int t = threadIdx.x;
    const int lane = t & 31;
    const int warp = t >> 5;
    const int v0 = blockIdx.x * 2;
    const int num0 = fvnum[v0];
    const int num1 = fvnum[v0 + 1];

    if ((num0 | num1) != 0) {
        // ---- stage points, small params, W2 panel ----
        if (t < 192) pts[t] = fv[(size_t)v0 * 96 + t];
        if (t < 96)  w1s[t] = W1[t];
        if (t >= 96 && t < 128) b1s[t - 96] = b1[t - 96];
        b2s[t] = b2[t];
#pragma unroll
        for (int i = 0; i < 8; i++) {       // 2048 float4 = full W2P panel
            const int idx = t + i * 256;
            const int g = idx >> 7, c4 = idx & 127;
            *(float4*)&bp[g * BPS + c4 * 4] =
                *(const float4*)&g_W2P[(g * 128 + c4) * 4];
        }
        __syncthreads();

        // ---- layer 1 -> h1p (pre-rounded to tf32) ----
        for (int idx = t; idx < 64 * 32; idx += NTHREADS) {
            const int p = idx >> 5, k = idx & 31;
            const float a = b1s[k]
                          + w1s[k * 3 + 0] * pts[p * 3 + 0]
                          + w1s[k * 3 + 1] * pts[p * 3 + 1]
                          + w1s[k * 3 + 2] * pts[p * 3 + 2];
            h1p[p * H1S + k] = to_tf32_rn(fmaxf(a, 0.0f));
        }
        __syncthreads();

        const int mg = warp & 1;            // voxel within CTA
        const int ng = warp >> 1;           // 64-col group
        const int arow = mg * 32 + (lane >> 2);
        const int my_num = mg ? num1 : num0;
        const bool m1_live = my_num > 16;
        const int j = lane & 3;
        const int bcol2 = (ng * 64 + (lane >> 2)) * 2;

        float acc[2][8][4];
#pragma unroll
        for (int s = 0; s < 2; s++)
#pragma unroll
            for (int i = 0; i < 8; i++)
#pragma unroll
                for (int q = 0; q < 4; q++) acc[s][i][q] = 0.0f;

        // ---- layer 2: [64x32] @ W2P, K=32 (4 k8 steps), 1xTF32 ----
#pragma unroll
        for (int k8 = 0; k8 < 4; k8++) {
            const int q2 = (k8 * 4 + j) * 2;
            const float2 A0 = *(const float2*)&h1p[arow * H1S + q2];
            const float2 A1 = *(const float2*)&h1p[(arow + 8) * H1S + q2];
            const float2 A2 = *(const float2*)&h1p[(arow + 16) * H1S + q2];
            const float2 A3 = *(const float2*)&h1p[(arow + 24) * H1S + q2];
            const float* brow = &bp[(k8 * 4 + j) * BPS + bcol2];
#pragma unroll
            for (int n8 = 0; n8 < 8; n8++) {
                const float2 B = *(const float2*)&brow[n8 * 16];
                mma_tf32(acc[0][n8], A0.x, A1.x, A0.y, A1.y, B.x, B.y);
                mma_tf32(acc[1][n8], A2.x, A3.x, A2.y, A3.y, B.x, B.y);
            }
        }

        // ---- h2p store: bias + relu + rn (pairs are naturally adjacent) ----
#pragma unroll
        for (int n8 = 0; n8 < 8; n8++) {
            const int col = ng * 64 + n8 * 8 + j * 2;
            const float bb0 = b2s[col], bb1 = b2s[col + 1];
            *(float2*)&h2p[arow * H2S + col] = make_float2(
                to_tf32_rn(fmaxf(acc[0][n8][0] + bb0, 0.f)),
                to_tf32_rn(fmaxf(acc[0][n8][1] + bb1, 0.f)));
            *(float2*)&h2p[(arow + 8) * H2S + col] = make_float2(
                to_tf32_rn(fmaxf(acc[0][n8][2] + bb0, 0.f)),
                to_tf32_rn(fmaxf(acc[0][n8][3] + bb1, 0.f)));
            *(float2*)&h2p[(arow + 16) * H2S + col] = make_float2(
                to_tf32_rn(fmaxf(acc[1][n8][0] + bb0, 0.f)),
                to_tf32_rn(fmaxf(acc[1][n8][1] + bb1, 0.f)));
            *(float2*)&h2p[(arow + 24) * H2S + col] = make_float2(
                to_tf32_rn(fmaxf(acc[1][n8][2] + bb0, 0.f)),
                to_tf32_rn(fmaxf(acc[1][n8][3] + bb1, 0.f)));
#pragma unroll
            for (int q = 0; q < 4; q++) { acc[0][n8][q] = 0.f; acc[1][n8][q] = 0.f; }
        }

        // ---- layer 3: C[64][256] = h2 @ W3P, 8 K-chunks of 32 ----
        float4 stage[8];
#pragma unroll
        for (int i = 0; i < 8; i++) {       // prefetch chunk 0
            const int idx = t + i * 256;
            stage[i] = *(const float4*)&g_W3P[idx * 4];
        }
        __syncthreads();                    // W2 panel reads complete
#pragma unroll
        for (int i = 0; i < 8; i++) {
            const int idx = t + i * 256;
            *(float4*)&bp[(idx >> 7) * BPS + (idx & 127) * 4] = stage[i];
        }
        __syncthreads();

        for (int kc = 0; kc < 8; kc++) {
            const bool more = (kc + 1 < 8);
            if (more) {
#pragma unroll
                for (int i = 0; i < 8; i++) {
                    const int idx = t + i * 256;
                    stage[i] = *(const float4*)&g_W3P[((kc + 1) * 2048 + idx) * 4];
                }
            }
            if (my_num > 0) {
#pragma unroll
                for (int k8 = 0; k8 < 4; k8++) {
                    const int q2 = ((kc * 4 + k8) * 4 + j) * 2;   // A pair offset
                    const float2 A0 = *(const float2*)&h2p[arow * H2S + q2];
                    const float2 A1 = *(const float2*)&h2p[(arow + 8) * H2S + q2];
                    float2 A2, A3;
                    if (m1_live) {
                        A2 = *(const float2*)&h2p[(arow + 16) * H2S + q2];
                        A3 = *(const float2*)&h2p[(arow + 24) * H2S + q2];
                    }
                    const float* brow = &bp[(k8 * 4 + j) * BPS + bcol2];
#pragma unroll
                    for (int n8 = 0; n8 < 8; n8++) {
                        const float2 B = *(const float2*)&brow[n8 * 16];
                        mma_tf32(acc[0][n8], A0.x, A1.x, A0.y, A1.y, B.x, B.y);
                        if (m1_live)
                            mma_tf32(acc[1][n8], A2.x, A3.x, A2.y, A3.y, B.x, B.y);
                    }
                }
            }
            __syncthreads();                // bp reads complete
            if (more) {
#pragma unroll
                for (int i = 0; i < 8; i++) {
                    const int idx = t + i * 256;
                    *(float4*)&bp[(idx >> 7) * BPS + (idx & 127) * 4] = stage[i];
                }
                __syncthreads();
            }
        }

        // ---- store C fragments into h2p (overlay; all A reads done) ----
#pragma unroll
        for (int n8 = 0; n8 < 8; n8++) {
            const int col = ng * 64 + n8 * 8 + j * 2;
            *(float2*)&h2p[arow * H2S + col] =
                make_float2(acc[0][n8][0], acc[0][n8][1]);
            *(float2*)&h2p[(arow + 8) * H2S + col] =
                make_float2(acc[0][n8][2], acc[0][n8][3]);
            *(float2*)&h2p[(arow + 16) * H2S + col] =
                make_float2(acc[1][n8][0], acc[1][n8][1]);
            *(float2*)&h2p[(arow + 24) * H2S + col] =
                make_float2(acc[1][n8][2], acc[1][n8][3]);
        }
        __syncthreads();
    }

    // ---- epilogue: per-voxel masked max + b3, or zfeat for empty ----
#pragma unroll
    for (int v = 0; v < 2; v++) {
        const int nv = v ? num1 : num0;
        float r;
        if (nv == 0) {
            r = g_zfeat[t];
        } else {
            float m = -CUDART_INF_F;
            const float* c = &h2p[v * 32 * H2S + t];
            for (int p = 0; p < nv; p++) m = fmaxf(m, c[p * H2S]);
            r = m + __ldg(&b3[t]);
        }
        out[(size_t)(v0 + v) * 256 + t] = r;
    }
}

// ---------------------------------------------------------------------------
// Launch. Inputs: Frustum_Voxel, Frustum_Voxel_num, W1,b1,W2,b2,W3,b3.
// Launch period 2 -> ncu -s 5 -c 1 lands on the main kernel.
// ---------------------------------------------------------------------------
extern "C" void kernel_launch(void* const* d_in, const int* in_sizes, int n_in,
                              void* d_out, int out_size) {
    const float* fv    = (const float*)d_in[0];
    const int*   fvnum = (const int*)  d_in[1];
    const float* W1    = (const float*)d_in[2];
    const float* b1    = (const float*)d_in[3];
    const float* W2    = (const float*)d_in[4];
    const float* b2    = (const float*)d_in[5];
    const float* W3    = (const float*)d_in[6];
    const float* b3    = (const float*)d_in[7];
    float* out = (float*)d_out;

    const int V = in_sizes[1];                  // 18432 voxels (even)
    const int smem_bytes =
        (576 + 64 * H1S + 64 * H2S + 16 * BPS) * 4;   // 113,408 B

    static bool attr_set = false;
    if (!attr_set) {
        cudaFuncSetAttribute(voxel_tc_kernel,
                             cudaFuncAttributeMaxDynamicSharedMemorySize,
                             smem_bytes);
        attr_set = true;
    }

    prep_kernel<<<257, 256>>>(W2, W3, b1, b2, b3);
    voxel_tc_kernel<<<V / 2, NTHREADS, smem_bytes>>>(fv, fvnum, W1, b1, b2, b3,
                                                     out);
}

// round 11
// speedup vs baseline: 1.0337x; 1.0337x over previous
#include <cuda_runtime.h>
#include <math_constants.h>
#include <cstdint>

// Problem constants (fixed by dataset: B=2, H=96, W=96, P=32)
#define NTHREADS 256
#define H1S 36    // h1 row stride: 36 % 32 == 4 -> LDS.64 frag loads hit the 2-wf floor
#define H2S 260   // h2/C row stride: 260 % 32 == 4 -> same
// B panel is fragment-major (no stride games needed): [k8][n8g][lane] float2

// Scratch (allocation-free rule: __device__ globals).
// Fragment-major, K-pair-permuted, tf32-rn weights:
//   slot (k8g, n8g, lane): j=lane&3, nsub=lane>>2, n=n8g*8+nsub,
//   pair index p = k8g*4+j -> channels (2p, 2p+1)   [matches A-side pairing]
__device__ float g_zfeat[256];
__device__ __align__(16) float g_W2F[4  * 32 * 32 * 2];   // 32 KB
__device__ __align__(16) float g_W3F[32 * 32 * 32 * 2];   // 256 KB

__device__ __forceinline__ float to_tf32_rn(float x) {
    uint32_t r;
    asm("cvt.rna.tf32.f32 %0, %1;" : "=r"(r) : "f"(x));
    return __uint_as_float(r);
}

// ---------------------------------------------------------------------------
// Prep (grid 257 x 256): build fragment-major W2F/W3F; block 256: zfeat.
// ---------------------------------------------------------------------------
__global__ void prep_kernel(const float* __restrict__ W2,
                            const float* __restrict__ W3,
                            const float* __restrict__ b1,
                            const float* __restrict__ b2,
                            const float* __restrict__ b3) {
    const int t = threadIdx.x;
    const int blk = blockIdx.x;
    if (blk < 128) {                         // W3F: 32768 float2 slots
        const int idx = blk * 256 + t;
        const int k8g = idx >> 10;
        const int n8g = (idx >> 5) & 31;
        const int lane = idx & 31;
        const int j = lane & 3, nsub = lane >> 2;
        const int n = n8g * 8 + nsub;
        const int p = k8g * 4 + j;           // pair index
        *(float2*)&g_W3F[idx * 2] = make_float2(
            to_tf32_rn(W3[n * 256 + 2 * p]),
            to_tf32_rn(W3[n * 256 + 2 * p + 1]));
    } else if (blk < 144) {                  // W2F: 4096 float2 slots
        const int idx = (blk - 128) * 256 + t;
        const int k8g = idx >> 10;
        const int n8g = (idx >> 5) & 31;
        const int lane = idx & 31;
        const int j = lane & 3, nsub = lane >> 2;
        const int n = n8g * 8 + nsub;
        const int p = k8g * 4 + j;
        *(float2*)&g_W2F[idx * 2] = make_float2(
            to_tf32_rn(W2[n * 32 + 2 * p]),
            to_tf32_rn(W2[n * 32 + 2 * p + 1]));
    } else if (blk == 256) {
        __shared__ float h1[32];
        __shared__ float h2[256];
        if (t < 32) h1[t] = fmaxf(b1[t], 0.0f);
        __syncthreads();
        float a = b2[t];
#pragma unroll 8
        for (int c = 0; c < 32; c++) a += W2[t * 32 + c] * h1[c];
        h2[t] = fmaxf(a, 0.0f);
        __syncthreads();
        float o = b3[t];
#pragma unroll 8
        for (int c = 0; c < 256; c++) o += W3[t * 256 + c] * h2[c];
        g_zfeat[t] = o;
    }
}

__device__ __forceinline__ void mma_tf32(float* d,
                                         float a0, float a1, float a2, float a3,
                                         float b0, float b1) {
    asm volatile(
        "mma.sync.aligned.m16n8k8.row.col.f32.tf32.tf32.f32 "
        "{%0,%1,%2,%3},{%4,%5,%6,%7},{%8,%9},{%0,%1,%2,%3};"
        : "+f"(d[0]), "+f"(d[1]), "+f"(d[2]), "+f"(d[3])
        : "r"(__float_as_uint(a0)), "r"(__float_as_uint(a1)),
          "r"(__float_as_uint(a2)), "r"(__float_as_uint(a3)),
          "r"(__float_as_uint(b0)), "r"(__float_as_uint(b1)));
}

// ---------------------------------------------------------------------------
// Main: one CTA / 2 voxels; 2 CTAs/SM (110.8 KB smem, 128 regs).
// Warp tile M=32 (one voxel) x N=64. Both GEMMs 1xTF32-RN.
// A: K-paired row-major (stride 260/36, bank-optimal LDS.64).
// B: fragment-major smem blocks (LDS.64 at base+lane*8, exactly 2 wf).
// Smem (floats): pts 192 | w1s 96 | b1s 32 | b2s 256 | h1p 64*H1S |
//                h2p 64*H2S (C overlay) | bp 8192 (fragment-major chunk)
// ---------------------------------------------------------------------------
__global__ void __launch_bounds__(NTHREADS, 2)
voxel_tc_kernel(const float* __restrict__ fv,     // [V][32][3]
                const int*   __restrict__ fvnum,  // [V]
                const float* __restrict__ W1,     // [32][3]
                const float* __restrict__ b1,     // [32]
                const float* __restrict__ b2,     // [256]
                const float* __restrict__ b3,     // [256]
                float* __restrict__ out)          // [V][256]
{
    extern __shared__ float sm[];
    float* pts = sm;                        // 192
    float* w1s = sm + 192;                  // 96
    float* b1s = sm + 288;                  // 32
    float* b2s = sm + 320;                  // 256
    float* h1p = sm + 576;                  // 64*H1S = 2304
    float* h2p = sm + 576 + 64 * H1S;       // 64*H2S = 16640 (later: C)
    float* bp  = sm + 576 + 64 * H1S + 64 * H2S;   // 8192

    const int t = threadIdx.x;
    const int lane = t & 31;
    const int warp = t >> 5;
    const int v0 = blockIdx.x * 2;
    const int num0 = fvnum[v0];
    const int num1 = fvnum[v0 + 1];

    if ((num0 | num1) != 0) {
        // ---- stage points, small params, W2F panel (linear copy) ----
        if (t < 192) pts[t] = fv[(size_t)v0 * 96 + t];
        if (t < 96)  w1s[t] = W1[t];
        if (t >= 96 && t < 128) b1s[t - 96] = b1[t - 96];
        b2s[t] = b2[t];
#pragma unroll
        for (int i = 0; i < 8; i++) {       // 2048 float4 = full W2F panel
            const int idx = t + i * 256;
            *(float4*)&bp[idx * 4] = *(const float4*)&g_W2F[idx * 4];
        }
        __syncthreads();

        // ---- layer 1 -> h1p (pre-rounded to tf32, natural channel order) ----
        for (int idx = t; idx < 64 * 32; idx += NTHREADS) {
            const int p = idx >> 5, k = idx & 31;
            const float a = b1s[k]
                          + w1s[k * 3 + 0] * pts[p * 3 + 0]
                          + w1s[k * 3 + 1] * pts[p * 3 + 1]
                          + w1s[k * 3 + 2] * pts[p * 3 + 2];
            h1p[p * H1S + k] = to_tf32_rn(fmaxf(a, 0.0f));
        }
        __syncthreads();

        const int mg = warp & 1;            // voxel within CTA
        const int ng = warp >> 1;           // 64-col group
        const int arow = mg * 32 + (lane >> 2);
        const int my_num = mg ? num1 : num0;
        const bool m1_live = my_num > 16;
        const int j = lane & 3;

        float acc[2][8][4];
#pragma unroll
        for (int s = 0; s < 2; s++)
#pragma unroll
            for (int i = 0; i < 8; i++)
#pragma unroll
                for (int q = 0; q < 4; q++) acc[s][i][q] = 0.0f;

        // ---- layer 2: [64x32] @ W2F, K=32 (4 k8 steps), 1xTF32 ----
#pragma unroll
        for (int k8 = 0; k8 < 4; k8++) {
            const int q2 = (k8 * 4 + j) * 2;              // A pair offset
            const float2 A0 = *(const float2*)&h1p[arow * H1S + q2];
            const float2 A1 = *(const float2*)&h1p[(arow + 8) * H1S + q2];
            const float2 A2 = *(const float2*)&h1p[(arow + 16) * H1S + q2];
            const float2 A3 = *(const float2*)&h1p[(arow + 24) * H1S + q2];
            const float* bf = &bp[((k8 * 32 + ng * 8) * 32 + lane) * 2];
#pragma unroll
            for (int n8 = 0; n8 < 8; n8++) {
                const float2 B = *(const float2*)&bf[n8 * 64];
                mma_tf32(acc[0][n8], A0.x, A1.x, A0.y, A1.y, B.x, B.y);
                mma_tf32(acc[1][n8], A2.x, A3.x, A2.y, A3.y, B.x, B.y);
            }
        }

        // ---- h2p store: bias + relu + rn (C cols are adjacent channel pairs) ----
#pragma unroll
        for (int n8 = 0; n8 < 8; n8++) {
            const int col = ng * 64 + n8 * 8 + j * 2;
            const float bb0 = b2s[col], bb1 = b2s[col + 1];
            *(float2*)&h2p[arow * H2S + col] = make_float2(
                to_tf32_rn(fmaxf(acc[0][n8][0] + bb0, 0.f)),
                to_tf32_rn(fmaxf(acc[0][n8][1] + bb1, 0.f)));
            *(float2*)&h2p[(arow + 8) * H2S + col] = make_float2(
                to_tf32_rn(fmaxf(acc[0][n8][2] + bb0, 0.f)),
                to_tf32_rn(fmaxf(acc[0][n8][3] + bb1, 0.f)));
            *(float2*)&h2p[(arow + 16) * H2S + col] = make_float2(
                to_tf32_rn(fmaxf(acc[1][n8][0] + bb0, 0.f)),
                to_tf32_rn(fmaxf(acc[1][n8][1] + bb1, 0.f)));
            *(float2*)&h2p[(arow + 24) * H2S + col] = make_float2(
                to_tf32_rn(fmaxf(acc[1][n8][2] + bb0, 0.f)),
                to_tf32_rn(fmaxf(acc[1][n8][3] + bb1, 0.f)));
#pragma unroll
            for (int q = 0; q < 4; q++) { acc[0][n8][q] = 0.f; acc[1][n8][q] = 0.f; }
        }

        // ---- layer 3: C[64][256] = h2 @ W3F, 8 K-chunks of 32 ----
        float4 stage[8];
#pragma unroll
        for (int i = 0; i < 8; i++)         // prefetch chunk 0
            stage[i] = *(const float4*)&g_W3F[(t + i * 256) * 4];
        __syncthreads();                    // W2F panel reads complete
#pragma unroll
        for (int i = 0; i < 8; i++)
            *(float4*)&bp[(t + i * 256) * 4] = stage[i];
        __syncthreads();

        for (int kc = 0; kc < 8; kc++) {
            const bool more = (kc + 1 < 8);
            if (more) {
#pragma unroll
                for (int i = 0; i < 8; i++) {
                    const int idx = t + i * 256;
                    stage[i] =
                        *(const float4*)&g_W3F[((kc + 1) * 2048 + idx) * 4];
                }
            }
            if (my_num > 0) {
#pragma unroll
                for (int k8 = 0; k8 < 4; k8++) {
                    const int q2 = ((kc * 4 + k8) * 4 + j) * 2;   // A pair offset
                    const float2 A0 = *(const float2*)&h2p[arow * H2S + q2];
                    const float2 A1 = *(const float2*)&h2p[(arow + 8) * H2S + q2];
                    float2 A2, A3;
                    if (m1_live) {
                        A2 = *(const float2*)&h2p[(arow + 16) * H2S + q2];
                        A3 = *(const float2*)&h2p[(arow + 24) * H2S + q2];
                    }
                    const float* bf = &bp[((k8 * 32 + ng * 8) * 32 + lane) * 2];
#pragma unroll
                    for (int n8 = 0; n8 < 8; n8++) {
                        const float2 B = *(const float2*)&bf[n8 * 64];
                        mma_tf32(acc[0][n8], A0.x, A1.x, A0.y, A1.y, B.x, B.y);
                        if (m1_live)
                            mma_tf32(acc[1][n8], A2.x, A3.x, A2.y, A3.y, B.x, B.y);
                    }
                }
            }
            __syncthreads();                // bp reads complete
            if (more) {
#pragma unroll
                for (int i = 0; i < 8; i++)
                    *(float4*)&bp[(t + i * 256) * 4] = stage[i];
                __syncthreads();
            }
        }

        // ---- store C fragments into h2p (overlay; all A reads done) ----
#pragma unroll
        for (int n8 = 0; n8 < 8; n8++) {
            const int col = ng * 64 + n8 * 8 + j * 2;
            *(float2*)&h2p[arow * H2S + col] =
                make_float2(acc[0][n8][0], acc[0][n8][1]);
            *(float2*)&h2p[(arow + 8) * H2S + col] =
                make_float2(acc[0][n8][2], acc[0][n8][3]);
            *(float2*)&h2p[(arow + 16) * H2S + col] =
                make_float2(acc[1][n8][0], acc[1][n8][1]);
            *(float2*)&h2p[(arow + 24) * H2S + col] =
                make_float2(acc[1][n8][2], acc[1][n8][3]);
        }
        __syncthreads();
    }

    // ---- epilogue: per-voxel masked max + b3, or zfeat for empty ----
#pragma unroll
    for (int v = 0; v < 2; v++) {
        const int nv = v ? num1 : num0;
        float r;
        if (nv == 0) {
            r = g_zfeat[t];
        } else {
            float m = -CUDART_INF_F;
            const float* c = &h2p[v * 32 * H2S + t];
            for (int p = 0; p < nv; p++) m = fmaxf(m, c[p * H2S]);
            r = m + __ldg(&b3[t]);
        }
        out[(size_t)(v0 + v) * 256 + t] = r;
    }
}

// ---------------------------------------------------------------------------
// Launch. Inputs: Frustum_Voxel, Frustum_Voxel_num, W1,b1,W2,b2,W3,b3.
// Launch period 2 -> ncu -s 5 -c 1 lands on the main kernel.
// ---------------------------------------------------------------------------
extern "C" void kernel_launch(void* const* d_in, const int* in_sizes, int n_in,
                              void* d_out, int out_size) {
    const float* fv    = (const float*)d_in[0];
    const int*   fvnum = (const int*)  d_in[1];
    const float* W1    = (const float*)d_in[2];
    const float* b1    = (const float*)d_in[3];
    const float* W2    = (const float*)d_in[4];
    const float* b2    = (const float*)d_in[5];
    const float* W3    = (const float*)d_in[6];
    const float* b3    = (const float*)d_in[7];
    float* out = (float*)d_out;

    const int V = in_sizes[1];                  // 18432 voxels (even)
    const int smem_bytes =
        (576 + 64 * H1S + 64 * H2S + 8192) * 4;   // 110,848 B

    static bool attr_set = false;
    if (!attr_set) {
        cudaFuncSetAttribute(voxel_tc_kernel,
                             cudaFuncAttributeMaxDynamicSharedMemorySize,
                             smem_bytes);
        attr_set = true;
    }

    prep_kernel<<<257, 256>>>(W2, W3, b1, b2, b3);
    voxel_tc_kernel<<<V / 2, NTHREADS, smem_bytes>>>(fv, fvnum, W1, b1, b2, b3,
                                                     out);
}

// round 12
// speedup vs baseline: 1.6715x; 1.6170x over previous
#include <cuda_runtime.h>
#include <math_constants.h>
#include <cstdint>

// Problem constants (fixed by dataset: B=2, H=96, W=96, P=32)
#define NTHREADS 256
#define H1S 40    // h1 row stride: 40 % 32 == 8 -> conflict-free LDS.64 phases
#define H2S 264   // h2/C row stride: 264 % 32 == 8 -> conflict-free

// Scratch (allocation-free rule: __device__ globals).
// Fragment-major, K-pair-permuted, tf32-rn weights (validated r10/r11):
//   slot (k8g, n8g, lane): j=lane&3, nsub=lane>>2, n=n8g*8+nsub,
//   pair p = k8g*4+j -> channels (2p, 2p+1).
// Padded by 2 k8-groups (zero-init) so prefetch may read past the end.
__device__ float g_zfeat[256];
__device__ __align__(16) float g_W2F[(4 + 2) * 1024 * 2];
__device__ __align__(16) float g_W3F[(32 + 2) * 1024 * 2];

__device__ __forceinline__ float to_tf32_rn(float x) {
    uint32_t r;
    asm("cvt.rna.tf32.f32 %0, %1;" : "=r"(r) : "f"(x));
    return __uint_as_float(r);
}

// ---------------------------------------------------------------------------
// Prep (grid 257 x 256): build fragment-major W2F/W3F; block 256: zfeat.
// ---------------------------------------------------------------------------
__global__ void prep_kernel(const float* __restrict__ W2,
                            const float* __restrict__ W3,
                            const float* __restrict__ b1,
                            const float* __restrict__ b2,
                            const float* __restrict__ b3) {
    const int t = threadIdx.x;
    const int blk = blockIdx.x;
    if (blk < 128) {                         // W3F: 32768 float2 slots
        const int idx = blk * 256 + t;
        const int k8g = idx >> 10;
        const int n8g = (idx >> 5) & 31;
        const int lane = idx & 31;
        const int j = lane & 3, nsub = lane >> 2;
        const int n = n8g * 8 + nsub;
        const int p = k8g * 4 + j;
        *(float2*)&g_W3F[idx * 2] = make_float2(
            to_tf32_rn(W3[n * 256 + 2 * p]),
            to_tf32_rn(W3[n * 256 + 2 * p + 1]));
    } else if (blk < 144) {                  // W2F: 4096 float2 slots
        const int idx = (blk - 128) * 256 + t;
        const int k8g = idx >> 10;
        const int n8g = (idx >> 5) & 31;
        const int lane = idx & 31;
        const int j = lane & 3, nsub = lane >> 2;
        const int n = n8g * 8 + nsub;
        const int p = k8g * 4 + j;
        *(float2*)&g_W2F[idx * 2] = make_float2(
            to_tf32_rn(W2[n * 32 + 2 * p]),
            to_tf32_rn(W2[n * 32 + 2 * p + 1]));
    } else if (blk == 256) {
        __shared__ float h1[32];
        __shared__ float h2[256];
        if (t < 32) h1[t] = fmaxf(b1[t], 0.0f);
        __syncthreads();
        float a = b2[t];
#pragma unroll 8
        for (int c = 0; c < 32; c++) a += W2[t * 32 + c] * h1[c];
        h2[t] = fmaxf(a, 0.0f);
        __syncthreads();
        float o = b3[t];
#pragma unroll 8
        for (int c = 0; c < 256; c++) o += W3[t * 256 + c] * h2[c];
        g_zfeat[t] = o;
    }
}

__device__ __forceinline__ void mma_tf32(float* d,
                                         float a0, float a1, float a2, float a3,
                                         float b0, float b1) {
    asm volatile(
        "mma.sync.aligned.m16n8k8.row.col.f32.tf32.tf32.f32 "
        "{%0,%1,%2,%3},{%4,%5,%6,%7},{%8,%9},{%0,%1,%2,%3};"
        : "+f"(d[0]), "+f"(d[1]), "+f"(d[2]), "+f"(d[3])
        : "r"(__float_as_uint(a0)), "r"(__float_as_uint(a1)),
          "r"(__float_as_uint(a2)), "r"(__float_as_uint(a3)),
          "r"(__float_as_uint(b0)), "r"(__float_as_uint(b1)));
}

// ---------------------------------------------------------------------------
// Main: ONE voxel per CTA, 256 threads (8 warps), warp tile M=32 x N=32.
// 3 CTAs/SM (36 KB static smem, <=80 regs): 24 warps.
// B operands: direct coalesced LDG.64 from fragment-major globals, double
// register-buffered (prefetch distance 2). No B smem, no mainloop barriers.
// Smem: pts 96 | w1s 96 | b1s 32 | b2s 256 | (pad) | h2p 32*H2S (h1 overlay, C overlay)
// ---------------------------------------------------------------------------
__global__ void __launch_bounds__(NTHREADS, 3)
voxel_tc_kernel(const float* __restrict__ fv,     // [V][32][3]
                const int*   __restrict__ fvnum,  // [V]
                const float* __restrict__ W1,     // [32][3]
                const float* __restrict__ b1,     // [32]
                const float* __restrict__ b2,     // [256]
                const float* __restrict__ b3,     // [256]
                float* __restrict__ out)          // [V][256]
{
    __shared__ float sm[576 + 32 * H2S];    // 9024 floats = 36096 B
    float* pts = sm;                        // 96
    float* w1s = sm + 96;                   // 96
    float* b1s = sm + 192;                  // 32
    float* b2s = sm + 224;                  // 256
    float* h2p = sm + 576;                  // 32*H2S (h1 overlay at same base)
    float* h1p = h2p;

    const int t = threadIdx.x;
    const int lane = t & 31;
    const int ng = t >> 5;                  // warp = N group (0..7)
    const int v = blockIdx.x;
    const int num = fvnum[v];

    if (num == 0) {                         // empty voxel: constant output
        out[(size_t)v * 256 + t] = g_zfeat[t];
        return;
    }

    const int j = lane & 3;
    const int arow = lane >> 2;
    const bool m1 = num > 16;
    // fragment slot base for (k8, n8l): (k8*32 + ng*4 + n8l)*32 + lane, x2 floats
    const int fbase = ((ng * 4) * 32 + lane) * 2;

    // ---- prefetch layer-2 B (k8 = 0,1) while staging runs ----
    float2 bA[4], bB[4];
#pragma unroll
    for (int n = 0; n < 4; n++) {
        bA[n] = *(const float2*)&g_W2F[fbase + n * 64];
        bB[n] = *(const float2*)&g_W2F[2048 + fbase + n * 64];
    }

    // ---- stage points + small params ----
    if (t < 96) pts[t] = fv[(size_t)v * 96 + t];
    else if (t < 192) w1s[t - 96] = W1[t - 96];
    else if (t < 224) b1s[t - 192] = b1[t - 192];
    b2s[t] = b2[t];
    __syncthreads();

    // ---- layer 1: 32 points x 32 channels -> h1p (tf32-rounded) ----
#pragma unroll
    for (int i = 0; i < 4; i++) {
        const int idx = t + i * 256;
        const int p = idx >> 5, k = idx & 31;
        const float a = b1s[k]
                      + w1s[k * 3 + 0] * pts[p * 3 + 0]
                      + w1s[k * 3 + 1] * pts[p * 3 + 1]
                      + w1s[k * 3 + 2] * pts[p * 3 + 2];
        h1p[p * H1S + k] = to_tf32_rn(fmaxf(a, 0.0f));
    }
    __syncthreads();

    float acc[2][4][4];
#pragma unroll
    for (int s = 0; s < 2; s++)
#pragma unroll
        for (int n = 0; n < 4; n++)
#pragma unroll
            for (int q = 0; q < 4; q++) acc[s][n][q] = 0.0f;

    // ---- layer 2: [32x32] @ W2F, 4 k8 steps, 1xTF32 ----
#pragma unroll
    for (int k8 = 0; k8 < 4; k8++) {
        float2 bc[4];
#pragma unroll
        for (int n = 0; n < 4; n++) bc[n] = (k8 & 1) ? bB[n] : bA[n];
        const int q2 = (k8 * 4 + j) * 2;
        const float2 A0 = *(const float2*)&h1p[arow * H1S + q2];
        const float2 A1 = *(const float2*)&h1p[(arow + 8) * H1S + q2];
        float2 A2, A3;
        if (m1) {
            A2 = *(const float2*)&h1p[(arow + 16) * H1S + q2];
            A3 = *(const float2*)&h1p[(arow + 24) * H1S + q2];
        }
#pragma unroll
        for (int n = 0; n < 4; n++) {
            mma_tf32(acc[0][n], A0.x, A1.x, A0.y, A1.y, bc[n].x, bc[n].y);
            if (m1)
                mma_tf32(acc[1][n], A2.x, A3.x, A2.y, A3.y, bc[n].x, bc[n].y);
        }
        // reload consumed buffer with k8+2 (padded arrays: safe at k8=2,3)
#pragma unroll
        for (int n = 0; n < 4; n++) {
            if (k8 & 1)
                bB[n] = *(const float2*)&g_W2F[(k8 + 2) * 2048 + fbase + n * 64];
            else
                bA[n] = *(const float2*)&g_W2F[(k8 + 2) * 2048 + fbase + n * 64];
        }
    }

    // ---- prefetch layer-3 B (k8 = 0,1) before the store barrier ----
#pragma unroll
    for (int n = 0; n < 4; n++) {
        bA[n] = *(const float2*)&g_W3F[fbase + n * 64];
        bB[n] = *(const float2*)&g_W3F[2048 + fbase + n * 64];
    }
    __syncthreads();                        // all h1 reads done (h1/h2 overlay)

    // ---- h2 store: bias + relu + rn ----
#pragma unroll
    for (int n = 0; n < 4; n++) {
        const int col = ng * 32 + n * 8 + j * 2;
        const float bb0 = b2s[col], bb1 = b2s[col + 1];
        *(float2*)&h2p[arow * H2S + col] = make_float2(
            to_tf32_rn(fmaxf(acc[0][n][0] + bb0, 0.f)),
            to_tf32_rn(fmaxf(acc[0][n][1] + bb1, 0.f)));
        *(float2*)&h2p[(arow + 8) * H2S + col] = make_float2(
            to_tf32_rn(fmaxf(acc[0][n][2] + bb0, 0.f)),
            to_tf32_rn(fmaxf(acc[0][n][3] + bb1, 0.f)));
        if (m1) {
            *(float2*)&h2p[(arow + 16) * H2S + col] = make_float2(
                to_tf32_rn(fmaxf(acc[1][n][0] + bb0, 0.f)),
                to_tf32_rn(fmaxf(acc[1][n][1] + bb1, 0.f)));
            *(float2*)&h2p[(arow + 24) * H2S + col] = make_float2(
                to_tf32_rn(fmaxf(acc[1][n][2] + bb0, 0.f)),
                to_tf32_rn(fmaxf(acc[1][n][3] + bb1, 0.f)));
        }
#pragma unroll
        for (int q = 0; q < 4; q++) { acc[0][n][q] = 0.f; acc[1][n][q] = 0.f; }
    }
    __syncthreads();                        // h2 ready for all warps

    // ---- layer 3: C[32][256] = h2 @ W3F, 32 k8 steps, barrier-free ----
    for (int k8 = 0; k8 < 32; k8 += 2) {
        {   // even step: consume bA, refill with k8+2
            const int q2 = (k8 * 4 + j) * 2;
            const float2 A0 = *(const float2*)&h2p[arow * H2S + q2];
            const float2 A1 = *(const float2*)&h2p[(arow + 8) * H2S + q2];
            float2 A2, A3;
            if (m1) {
                A2 = *(const float2*)&h2p[(arow + 16) * H2S + q2];
                A3 = *(const float2*)&h2p[(arow + 24) * H2S + q2];
            }
#pragma unroll
            for (int n = 0; n < 4; n++) {
                mma_tf32(acc[0][n], A0.x, A1.x, A0.y, A1.y, bA[n].x, bA[n].y);
                if (m1)
                    mma_tf32(acc[1][n], A2.x, A3.x, A2.y, A3.y, bA[n].x, bA[n].y);
            }
#pragma unroll
            for (int n = 0; n < 4; n++)
                bA[n] = *(const float2*)&g_W3F[(k8 + 2) * 2048 + fbase + n * 64];
        }
        {   // odd step: consume bB, refill with k8+3
            const int q2 = ((k8 + 1) * 4 + j) * 2;
            const float2 A0 = *(const float2*)&h2p[arow * H2S + q2];
            const float2 A1 = *(const float2*)&h2p[(arow + 8) * H2S + q2];
            float2 A2, A3;
            if (m1) {
                A2 = *(const float2*)&h2p[(arow + 16) * H2S + q2];
                A3 = *(const float2*)&h2p[(arow + 24) * H2S + q2];
            }
#pragma unroll
            for (int n = 0; n < 4; n++) {
                mma_tf32(acc[0][n], A0.x, A1.x, A0.y, A1.y, bB[n].x, bB[n].y);
                if (m1)
                    mma_tf32(acc[1][n], A2.x, A3.x, A2.y, A3.y, bB[n].x, bB[n].y);
            }
#pragma unroll
            for (int n = 0; n < 4; n++)
                bB[n] = *(const float2*)&g_W3F[(k8 + 3) * 2048 + fbase + n * 64];
        }
    }
    __syncthreads();                        // all h2 reads done (C overlay)

    // ---- store C into h2p ----
#pragma unroll
    for (int n = 0; n < 4; n++) {
        const int col = ng * 32 + n * 8 + j * 2;
        *(float2*)&h2p[arow * H2S + col] = make_float2(acc[0][n][0], acc[0][n][1]);
        *(float2*)&h2p[(arow + 8) * H2S + col] =
            make_float2(acc[0][n][2], acc[0][n][3]);
        if (m1) {
            *(float2*)&h2p[(arow + 16) * H2S + col] =
                make_float2(acc[1][n][0], acc[1][n][1]);
            *(float2*)&h2p[(arow + 24) * H2S + col] =
                make_float2(acc[1][n][2], acc[1][n][3]);
        }
    }
    __syncthreads();

    // ---- epilogue: masked max over valid rows + b3 ----
    float m = -CUDART_INF_F;
    for (int p = 0; p < num; p++) m = fmaxf(m, h2p[p * H2S + t]);
    out[(size_t)v * 256 + t] = m + __ldg(&b3[t]);
}

// ---------------------------------------------------------------------------
// Launch. Inputs: Frustum_Voxel, Frustum_Voxel_num, W1,b1,W2,b2,W3,b3.
// Launch period 2 -> ncu -s 5 -c 1 lands on the main kernel.
// ---------------------------------------------------------------------------
extern "C" void kernel_launch(void* const* d_in, const int* in_sizes, int n_in,
                              void* d_out, int out_size) {
    const float* fv    = (const float*)d_in[0];
    const int*   fvnum = (const int*)  d_in[1];
    const float* W1    = (const float*)d_in[2];
    const float* b1    = (const float*)d_in[3];
    const float* W2    = (const float*)d_in[4];
    const float* b2    = (const float*)d_in[5];
    const float* W3    = (const float*)d_in[6];
    const float* b3    = (const float*)d_in[7];
    float* out = (float*)d_out;

    const int V = in_sizes[1];                  // 18432 voxels

    prep_kernel<<<257, 256>>>(W2, W3, b1, b2, b3);
    voxel_tc_kernel<<<V, NTHREADS>>>(fv, fvnum, W1, b1, b2, b3, out);
}

// round 13
// speedup vs baseline: 1.7005x; 1.0174x over previous
#include <cuda_runtime.h>
#include <math_constants.h>
#include <cstdint>

// Problem constants (fixed by dataset: B=2, H=96, W=96, P=32)
#define NTHREADS 256
#define H1S 40    // h1 row stride: 40 % 32 == 8 -> conflict-free LDS.64 phases
#define H2S 264   // h2/C row stride: 264 % 32 == 8 -> conflict-free

// Scratch (allocation-free rule: __device__ globals).
// Fragment-major, K-pair-permuted, tf32-rn weights (validated r10-r12):
//   slot (k8g, n8g, lane): j=lane&3, nsub=lane>>2, n=n8g*8+nsub,
//   pair p = k8g*4+j -> channels (2p, 2p+1).
// Padded by 2 k8-groups (zero-init) so prefetch may read past the end.
__device__ float g_zfeat[256];
__device__ __align__(16) float g_W2F[(4 + 2) * 1024 * 2];
__device__ __align__(16) float g_W3F[(32 + 2) * 1024 * 2];

__device__ __forceinline__ float to_tf32_rn(float x) {
    uint32_t r;
    asm("cvt.rna.tf32.f32 %0, %1;" : "=r"(r) : "f"(x));
    return __uint_as_float(r);
}

// ---------------------------------------------------------------------------
// Prep (grid 257 x 256): build fragment-major W2F/W3F; block 256: zfeat.
// ---------------------------------------------------------------------------
__global__ void prep_kernel(const float* __restrict__ W2,
                            const float* __restrict__ W3,
                            const float* __restrict__ b1,
                            const float* __restrict__ b2,
                            const float* __restrict__ b3) {
    const int t = threadIdx.x;
    const int blk = blockIdx.x;
    if (blk < 128) {                         // W3F: 32768 float2 slots
        const int idx = blk * 256 + t;
        const int k8g = idx >> 10;
        const int n8g = (idx >> 5) & 31;
        const int lane = idx & 31;
        const int j = lane & 3, nsub = lane >> 2;
        const int n = n8g * 8 + nsub;
        const int p = k8g * 4 + j;
        *(float2*)&g_W3F[idx * 2] = make_float2(
            to_tf32_rn(W3[n * 256 + 2 * p]),
            to_tf32_rn(W3[n * 256 + 2 * p + 1]));
    } else if (blk < 144) {                  // W2F: 4096 float2 slots
        const int idx = (blk - 128) * 256 + t;
        const int k8g = idx >> 10;
        const int n8g = (idx >> 5) & 31;
        const int lane = idx & 31;
        const int j = lane & 3, nsub = lane >> 2;
        const int n = n8g * 8 + nsub;
        const int p = k8g * 4 + j;
        *(float2*)&g_W2F[idx * 2] = make_float2(
            to_tf32_rn(W2[n * 32 + 2 * p]),
            to_tf32_rn(W2[n * 32 + 2 * p + 1]));
    } else if (blk == 256) {
        __shared__ float h1[32];
        __shared__ float h2[256];
        if (t < 32) h1[t] = fmaxf(b1[t], 0.0f);
        __syncthreads();
        float a = b2[t];
#pragma unroll 8
        for (int c = 0; c < 32; c++) a += W2[t * 32 + c] * h1[c];
        h2[t] = fmaxf(a, 0.0f);
        __syncthreads();
        float o = b3[t];
#pragma unroll 8
        for (int c = 0; c < 256; c++) o += W3[t * 256 + c] * h2[c];
        g_zfeat[t] = o;
    }
}

__device__ __forceinline__ void mma_tf32(float* d,
                                         float a0, float a1, float a2, float a3,
                                         float b0, float b1) {
    asm volatile(
        "mma.sync.aligned.m16n8k8.row.col.f32.tf32.tf32.f32 "
        "{%0,%1,%2,%3},{%4,%5,%6,%7},{%8,%9},{%0,%1,%2,%3};"
        : "+f"(d[0]), "+f"(d[1]), "+f"(d[2]), "+f"(d[3])
        : "r"(__float_as_uint(a0)), "r"(__float_as_uint(a1)),
          "r"(__float_as_uint(a2)), "r"(__float_as_uint(a3)),
          "r"(__float_as_uint(b0)), "r"(__float_as_uint(b1)));
}

// ---------------------------------------------------------------------------
// Main: TWO voxels per CTA, 256 threads (8 warps), warp tile M=64 x N=32.
// Each B fragment is register-reused across 4 M-tiles -> per-voxel L1 read
// bytes drop ~29% vs M=32 tiles, and B LDG (L2) traffic halves.
// 2 CTAs/SM (70 KB dynamic smem, <=128 regs). Barrier-free LDG-double-
// buffered B mainloop (prefetch distance 2). Per-16-row-tile liveness skip.
// Smem (floats): pts 192 | w1s 96 | b1s 32 | b2s 256 | h2p 64*H2S
//                (h1 overlay at h2p base, C overlay after GEMM)
// ---------------------------------------------------------------------------
__global__ void __launch_bounds__(NTHREADS, 2)
voxel_tc_kernel(const float* __restrict__ fv,     // [V][32][3]
                const int*   __restrict__ fvnum,  // [V]
                const float* __restrict__ W1,     // [32][3]
                const float* __restrict__ b1,     // [32]
                const float* __restrict__ b2,     // [256]
                const float* __restrict__ b3,     // [256]
                float* __restrict__ out)          // [V][256]
{
    extern __shared__ float sm[];
    float* pts = sm;                        // 192
    float* w1s = sm + 192;                  // 96
    float* b1s = sm + 288;                  // 32
    float* b2s = sm + 320;                  // 256
    float* h2p = sm + 576;                  // 64*H2S (h1/C overlay)
    float* h1p = h2p;

    const int t = threadIdx.x;
    const int lane = t & 31;
    const int ng = t >> 5;                  // warp = N group (0..7), 32 cols
    const int v0 = blockIdx.x * 2;
    const int num0 = fvnum[v0];
    const int num1 = fvnum[v0 + 1];

    if ((num0 | num1) == 0) {               // both empty: constant outputs
        out[(size_t)v0 * 256 + t] = g_zfeat[t];
        out[(size_t)(v0 + 1) * 256 + t] = g_zfeat[t];
        return;
    }

    const int j = lane & 3;
    const int arow = lane >> 2;
    bool live[4];
    live[0] = num0 > 0;  live[1] = num0 > 16;
    live[2] = num1 > 0;  live[3] = num1 > 16;
    // fragment slot base for (k8, n8l): (k8*32 + ng*4 + n8l)*32 + lane, x2
    const int fbase = ((ng * 4) * 32 + lane) * 2;

    // ---- prefetch layer-2 B (k8 = 0,1) while staging runs ----
    float2 bA[4], bB[4];
#pragma unroll
    for (int n = 0; n < 4; n++) {
        bA[n] = *(const float2*)&g_W2F[fbase + n * 64];
        bB[n] = *(const float2*)&g_W2F[2048 + fbase + n * 64];
    }

    // ---- stage points (2 voxels) + small params ----
    if (t < 192) pts[t] = fv[(size_t)v0 * 96 + t];
    else if (t < 224) b1s[t - 192] = b1[t - 192];
    if (t >= 224 && t < 224 + 32) {}        // (hole; w1s loaded below)
    if (t < 96) w1s[t] = W1[t];             // small dual-duty loads are fine
    b2s[t] = b2[t];
    __syncthreads();

    // ---- layer 1: 64 rows x 32 channels -> h1p (tf32-rounded) ----
#pragma unroll
    for (int i = 0; i < 8; i++) {
        const int idx = t + i * 256;
        const int p = idx >> 5, k = idx & 31;
        const float a = b1s[k]
                      + w1s[k * 3 + 0] * pts[p * 3 + 0]
                      + w1s[k * 3 + 1] * pts[p * 3 + 1]
                      + w1s[k * 3 + 2] * pts[p * 3 + 2];
        h1p[p * H1S + k] = to_tf32_rn(fmaxf(a, 0.0f));
    }
    __syncthreads();

    float acc[4][4][4];                     // [Mtile][n8][frag]
#pragma unroll
    for (int s = 0; s < 4; s++)
#pragma unroll
        for (int n = 0; n < 4; n++)
#pragma unroll
            for (int q = 0; q < 4; q++) acc[s][n][q] = 0.0f;

    // ---- layer 2: [64x32] @ W2F, 4 k8 steps, 1xTF32 ----
#pragma unroll
    for (int k8 = 0; k8 < 4; k8++) {
        float2 bc[4];
#pragma unroll
        for (int n = 0; n < 4; n++) bc[n] = (k8 & 1) ? bB[n] : bA[n];
        const int q2 = (k8 * 4 + j) * 2;
#pragma unroll
        for (int s = 0; s < 4; s++) {
            if (live[s]) {
                const float2 A0 = *(const float2*)&h1p[(s * 16 + arow) * H1S + q2];
                const float2 A1 = *(const float2*)&h1p[(s * 16 + arow + 8) * H1S + q2];
#pragma unroll
                for (int n = 0; n < 4; n++)
                    mma_tf32(acc[s][n], A0.x, A1.x, A0.y, A1.y, bc[n].x, bc[n].y);
            }
        }
#pragma unroll
        for (int n = 0; n < 4; n++) {
            if (k8 & 1)
                bB[n] = *(const float2*)&g_W2F[(k8 + 2) * 2048 + fbase + n * 64];
            else
                bA[n] = *(const float2*)&g_W2F[(k8 + 2) * 2048 + fbase + n * 64];
        }
    }

    // ---- prefetch layer-3 B (k8 = 0,1) before the store barrier ----
#pragma unroll
    for (int n = 0; n < 4; n++) {
        bA[n] = *(const float2*)&g_W3F[fbase + n * 64];
        bB[n] = *(const float2*)&g_W3F[2048 + fbase + n * 64];
    }
    __syncthreads();                        // all h1 reads done (h1/h2 overlay)

    // ---- h2 store: bias + relu + rn ----
#pragma unroll
    for (int s = 0; s < 4; s++) {
        if (live[s]) {
#pragma unroll
            for (int n = 0; n < 4; n++) {
                const int col = ng * 32 + n * 8 + j * 2;
                const float bb0 = b2s[col], bb1 = b2s[col + 1];
                *(float2*)&h2p[(s * 16 + arow) * H2S + col] = make_float2(
                    to_tf32_rn(fmaxf(acc[s][n][0] + bb0, 0.f)),
                    to_tf32_rn(fmaxf(acc[s][n][1] + bb1, 0.f)));
                *(float2*)&h2p[(s * 16 + arow + 8) * H2S + col] = make_float2(
                    to_tf32_rn(fmaxf(acc[s][n][2] + bb0, 0.f)),
                    to_tf32_rn(fmaxf(acc[s][n][3] + bb1, 0.f)));
            }
        }
#pragma unroll
        for (int n = 0; n < 4; n++)
#pragma unroll
            for (int q = 0; q < 4; q++) acc[s][n][q] = 0.0f;
    }
    __syncthreads();                        // h2 ready for all warps

    // ---- layer 3: C[64][256] = h2 @ W3F, 32 k8 steps, barrier-free ----
    for (int k8 = 0; k8 < 32; k8 += 2) {
#pragma unroll
        for (int half = 0; half < 2; half++) {
            const int kk = k8 + half;
            const int q2 = (kk * 4 + j) * 2;
#pragma unroll
            for (int s = 0; s < 4; s++) {
                if (live[s]) {
                    const float2 A0 =
                        *(const float2*)&h2p[(s * 16 + arow) * H2S + q2];
                    const float2 A1 =
                        *(const float2*)&h2p[(s * 16 + arow + 8) * H2S + q2];
#pragma unroll
                    for (int n = 0; n < 4; n++) {
                        const float2 B = half ? bB[n] : bA[n];
                        mma_tf32(acc[s][n], A0.x, A1.x, A0.y, A1.y, B.x, B.y);
                    }
                }
            }
#pragma unroll
            for (int n = 0; n < 4; n++) {   // refill consumed buffer (kk+2)
                if (half)
                    bB[n] = *(const float2*)&g_W3F[(kk + 2) * 2048 + fbase + n * 64];
                else
                    bA[n] = *(const float2*)&g_W3F[(kk + 2) * 2048 + fbase + n * 64];
            }
        }
    }
    __syncthreads();                        // all h2 reads done (C overlay)

    // ---- store C into h2p ----
#pragma unroll
    for (int s = 0; s < 4; s++) {
        if (live[s]) {
#pragma unroll
            for (int n = 0; n < 4; n++) {
                const int col = ng * 32 + n * 8 + j * 2;
                *(float2*)&h2p[(s * 16 + arow) * H2S + col] =
                    make_float2(acc[s][n][0], acc[s][n][1]);
                *(float2*)&h2p[(s * 16 + arow + 8) * H2S + col] =
                    make_float2(acc[s][n][2], acc[s][n][3]);
            }
        }
    }
    __syncthreads();

    // ---- epilogue: per-voxel masked max over valid rows + b3 / zfeat ----
#pragma unroll
    for (int v = 0; v < 2; v++) {
        const int nv = v ? num1 : num0;
        float r;
        if (nv == 0) {
            r = g_zfeat[t];
        } else {
            float m = -CUDART_INF_F;
            const float* c = &h2p[v * 32 * H2S + t];
            for (int p = 0; p < nv; p++) m = fmaxf(m, c[p * H2S]);
            r = m + __ldg(&b3[t]);
        }
        out[(size_t)(v0 + v) * 256 + t] = r;
    }
}

// ---------------------------------------------------------------------------
// Launch. Inputs: Frustum_Voxel, Frustum_Voxel_num, W1,b1,W2,b2,W3,b3.
// Launch period 2 -> ncu -s 5 -c 1 lands on the main kernel.
// ---------------------------------------------------------------------------
extern "C" void kernel_launch(void* const* d_in, const int* in_sizes, int n_in,
                              void* d_out, int out_size) {
    const float* fv    = (const float*)d_in[0];
    const int*   fvnum = (const int*)  d_in[1];
    const float* W1    = (const float*)d_in[2];
    const float* b1    = (const float*)d_in[3];
    const float* W2    = (const float*)d_in[4];
    const float* b2    = (const float*)d_in[5];
    const float* W3    = (const float*)d_in[6];
    const float* b3    = (const float*)d_in[7];
    float* out = (float*)d_out;

    const int V = in_sizes[1];                  // 18432 voxels (even)
    const int smem_bytes = (576 + 64 * H2S) * 4;   // 69,888 B

    static bool attr_set = false;
    if (!attr_set) {
        cudaFuncSetAttribute(voxel_tc_kernel,
                             cudaFuncAttributeMaxDynamicSharedMemorySize,
                             smem_bytes);
        attr_set = true;
    }

    prep_kernel<<<257, 256>>>(W2, W3, b1, b2, b3);
    voxel_tc_kernel<<<V / 2, NTHREADS, smem_bytes>>>(fv, fvnum, W1, b1, b2, b3,
                                                     out);
}

// round 15
// speedup vs baseline: 2.6501x; 1.5584x over previous
#include <cuda_runtime.h>
#include <cuda_fp16.h>
#include <math_constants.h>
#include <cstdint>

// Problem constants (fixed by dataset: B=2, H=96, W=96, P=32)
#define NTHREADS 256
#define RS2 136   // h1/h2 row stride in half2 units: 544 B == 32 (mod 128) ->
                  // conflict-free LDS.64 fragment phases
#define CS  264   // C row stride (floats): 1056 B == 32 (mod 128)

// Scratch (allocation-free rule: __device__ globals).
// Fragment-major fp16 weights for mma.m16n8k16.f16 (B col-major fragment):
//   slot (k16, n8g, lane): j=lane&3, nsub=lane>>2, n=n8g*8+nsub,
//   .x = half2(W[n][k16*16+2j],   W[n][k16*16+2j+1])   (= frag b0, pair j)
//   .y = half2(W[n][k16*16+8+2j], W[n][k16*16+8+2j+1]) (= frag b1, pair j+4)
// W3H padded by 2 k16 groups (zero) so the distance-2 prefetch may over-read.
__device__ float g_zfeat[256];
__device__ __align__(16) uint2 g_W2H[2 * 1024];
__device__ __align__(16) uint2 g_W3H[(16 + 2) * 1024];

// ---------------------------------------------------------------------------
// Prep (grid 73 x 256): blocks 0-63 W3H, 64-71 W2H, 72 zfeat (full fp32).
// ---------------------------------------------------------------------------
__global__ void prep_kernel(const float* __restrict__ W2,
                            const float* __restrict__ W3,
                            const float* __restrict__ b1,
                            const float* __restrict__ b2,
                            const float* __restrict__ b3) {
    const int t = threadIdx.x;
    const int blk = blockIdx.x;
    if (blk < 64) {                          // W3H: 16384 uint2 slots
        const int idx = blk * 256 + t;
        const int k16 = idx >> 10;
        const int n8g = (idx >> 5) & 31;
        const int lane = idx & 31;
        const int j = lane & 3, nsub = lane >> 2;
        const int n = n8g * 8 + nsub;
        const int kb = k16 * 16;
        const half2 lo = __floats2half2_rn(W3[n * 256 + kb + 2 * j],
                                           W3[n * 256 + kb + 2 * j + 1]);
        const half2 hi = __floats2half2_rn(W3[n * 256 + kb + 8 + 2 * j],
                                           W3[n * 256 + kb + 8 + 2 * j + 1]);
        uint2 u;
        u.x = *(const uint32_t*)&lo;
        u.y = *(const uint32_t*)&hi;
        g_W3H[idx] = u;
    } else if (blk < 72) {                   // W2H: 2048 uint2 slots
        const int idx = (blk - 64) * 256 + t;
        const int k16 = idx >> 10;
        const int n8g = (idx >> 5) & 31;
        const int lane = idx & 31;
        const int j = lane & 3, nsub = lane >> 2;
        const int n = n8g * 8 + nsub;
        const int kb = k16 * 16;
        const half2 lo = __floats2half2_rn(W2[n * 32 + kb + 2 * j],
                                           W2[n * 32 + kb + 2 * j + 1]);
        const half2 hi = __floats2half2_rn(W2[n * 32 + kb + 8 + 2 * j],
                                           W2[n * 32 + kb + 8 + 2 * j + 1]);
        uint2 u;
        u.x = *(const uint32_t*)&lo;
        u.y = *(const uint32_t*)&hi;
        g_W2H[idx] = u;
    } else {
        __shared__ float h1[32];
        __shared__ float h2[256];
        if (t < 32) h1[t] = fmaxf(b1[t], 0.0f);
        __syncthreads();
        float a = b2[t];
#pragma unroll 8
        for (int c = 0; c < 32; c++) a += W2[t * 32 + c] * h1[c];
        h2[t] = fmaxf(a, 0.0f);
        __syncthreads();
        float o = b3[t];
#pragma unroll 8
        for (int c = 0; c < 256; c++) o += W3[t * 256 + c] * h2[c];
        g_zfeat[t] = o;
    }
}

__device__ __forceinline__ void mma_f16(float* d,
                                        uint32_t a0, uint32_t a1,
                                        uint32_t a2, uint32_t a3,
                                        uint32_t b0, uint32_t b1) {
    asm volatile(
        "mma.sync.aligned.m16n8k16.row.col.f32.f16.f16.f32 "
        "{%0,%1,%2,%3},{%4,%5,%6,%7},{%8,%9},{%0,%1,%2,%3};"
        : "+f"(d[0]), "+f"(d[1]), "+f"(d[2]), "+f"(d[3])
        : "r"(a0), "r"(a1), "r"(a2), "r"(a3), "r"(b0), "r"(b1));
}

// ---------------------------------------------------------------------------
// Main: ONE voxel per CTA, 256 threads (8 warps), warp tile M=32 x N=32,
// fp16 m16n8k16 (f32 accum). 3 CTAs/SM (35.7 KB static smem, <=84 regs).
// A storage K-permuted: half2 pos 2j <-> pair j, 2j+1 <-> pair j+4, so each
// fragment half (a0,a2) or (a1,a3) is one LDS.64. B: fragment-major LDG.64,
// double register-buffered, barrier-free mainloop. C kept fp32 in smem.
// ---------------------------------------------------------------------------
__global__ void __launch_bounds__(NTHREADS, 3)
voxel_tc_kernel(const float* __restrict__ fv,     // [V][32][3]
                const int*   __restrict__ fvnum,  // [V]
                const float* __restrict__ W1,     // [32][3]
                const float* __restrict__ b1,     // [32]
                const float* __restrict__ b2,     // [256]
                const float* __restrict__ b3,     // [256]
                float* __restrict__ out)          // [V][256]
{
    __shared__ float sm[480 + 32 * CS];     // 8928 floats = 35,712 B
    float* pts  = sm;                       // 96
    float* w1s  = sm + 96;                  // 96
    float* b1s  = sm + 192;                 // 32
    float* b2s  = sm + 224;                 // 256
    float* cbuf = sm + 480;                 // 32*CS f32 (C); h1/h2 half overlay
    half2* h2v  = (half2*)cbuf;             // rows: RS2 half2 stride
    half*  h1h  = (half*)cbuf;

    const int t = threadIdx.x;
    const int lane = t & 31;
    const int ng = t >> 5;                  // warp = N group (0..7), 32 cols
    const int v = blockIdx.x;
    const int num = fvnum[v];

    if (num == 0) {                         // empty voxel: constant output
        out[(size_t)v * 256 + t] = g_zfeat[t];
        return;
    }

    const int j = lane & 3;
    const int arow = lane >> 2;
    const bool m1 = num > 16;
    const int fslot = ng * 128 + lane;      // fragment-major slot base

    // ---- prefetch layer-2 B (both k16 groups) while staging runs ----
    uint2 bA[4], bB[4];
#pragma unroll
    for (int n = 0; n < 4; n++) {
        bA[n] = g_W2H[fslot + n * 32];
        bB[n] = g_W2H[1024 + fslot + n * 32];
    }

    // ---- stage points + small params ----
    if (t < 96) pts[t] = fv[(size_t)v * 96 + t];
    else if (t < 192) w1s[t - 96] = W1[t - 96];
    else if (t < 224) b1s[t - 192] = b1[t - 192];
    b2s[t] = b2[t];
    __syncthreads();

    // ---- layer 1: 32 pts x 32 ch -> h1 (fp16, K-pair-permuted storage) ----
#pragma unroll
    for (int i = 0; i < 4; i++) {
        const int idx = t + i * 256;
        const int p = idx >> 5, k = idx & 31;
        const float a = b1s[k]
                      + w1s[k * 3 + 0] * pts[p * 3 + 0]
                      + w1s[k * 3 + 1] * pts[p * 3 + 1]
                      + w1s[k * 3 + 2] * pts[p * 3 + 2];
        const int q = k >> 1, g16 = q >> 3, jj = q & 7;
        const int pos = g16 * 8 + ((jj < 4) ? 2 * jj : 2 * (jj - 4) + 1);
        h1h[p * (RS2 * 2) + pos * 2 + (k & 1)] = __float2half_rn(fmaxf(a, 0.f));
    }
    __syncthreads();

    float acc[2][4][4];                     // [Mtile][n8][frag]
#pragma unroll
    for (int s = 0; s < 2; s++)
#pragma unroll
        for (int n = 0; n < 4; n++)
#pragma unroll
            for (int q = 0; q < 4; q++) acc[s][n][q] = 0.0f;

    // ---- layer 2: [32x32] @ W2H, 2 k16 steps ----
#pragma unroll
    for (int k16 = 0; k16 < 2; k16++) {
        const int ap = k16 * 8 + 2 * j;     // half2 storage pos of (pair j, j+4)
        const uint2 U0 = *(const uint2*)&h2v[arow * RS2 + ap];
        const uint2 U1 = *(const uint2*)&h2v[(arow + 8) * RS2 + ap];
        uint2 U2, U3;
        if (m1) {
            U2 = *(const uint2*)&h2v[(arow + 16) * RS2 + ap];
            U3 = *(const uint2*)&h2v[(arow + 24) * RS2 + ap];
        }
#pragma unroll
        for (int n = 0; n < 4; n++) {
            const uint2 B = k16 ? bB[n] : bA[n];
            mma_f16(acc[0][n], U0.x, U1.x, U0.y, U1.y, B.x, B.y);
            if (m1) mma_f16(acc[1][n], U2.x, U3.x, U2.y, U3.y, B.x, B.y);
        }
    }

    // ---- prefetch layer-3 B (k16 = 0,1) before the store barrier ----
#pragma unroll
    for (int n = 0; n < 4; n++) {
        bA[n] = g_W3H[fslot + n * 32];
        bB[n] = g_W3H[1024 + fslot + n * 32];
    }
    __syncthreads();                        // all h1 reads done (overlay)

    // ---- h2 store: bias + relu -> half2, K-pair-permuted positions ----
#pragma unroll
    for (int s = 0; s < 2; s++) {
        if (s == 0 || m1) {
#pragma unroll
            for (int n = 0; n < 4; n++) {
                const int n8g = ng * 4 + n;
                const int col = n8g * 8 + 2 * j;          // channel index
                const int pos = (n8g >> 1) * 8 + 2 * j + (n8g & 1);
                const float bb0 = b2s[col], bb1 = b2s[col + 1];
                h2v[(s * 16 + arow) * RS2 + pos] = __floats2half2_rn(
                    fmaxf(acc[s][n][0] + bb0, 0.f),
                    fmaxf(acc[s][n][1] + bb1, 0.f));
                h2v[(s * 16 + arow + 8) * RS2 + pos] = __floats2half2_rn(
                    fmaxf(acc[s][n][2] + bb0, 0.f),
                    fmaxf(acc[s][n][3] + bb1, 0.f));
            }
        }
#pragma unroll
        for (int n = 0; n < 4; n++)
#pragma unroll
            for (int q = 0; q < 4; q++) acc[s][n][q] = 0.0f;
    }
    __syncthreads();                        // h2 ready for all warps

    // ---- layer 3: C[32][256] = h2 @ W3H, 16 k16 steps, barrier-free ----
    for (int k16 = 0; k16 < 16; k16 += 2) {
#pragma unroll
        for (int half_ = 0; half_ < 2; half_++) {
            const int kk = k16 + half_;
            const int ap = kk * 8 + 2 * j;
            const uint2 U0 = *(const uint2*)&h2v[arow * RS2 + ap];
            const uint2 U1 = *(const uint2*)&h2v[(arow + 8) * RS2 + ap];
            uint2 U2, U3;
            if (m1) {
                U2 = *(const uint2*)&h2v[(arow + 16) * RS2 + ap];
                U3 = *(const uint2*)&h2v[(arow + 24) * RS2 + ap];
            }
#pragma unroll
            for (int n = 0; n < 4; n++) {
                const uint2 B = half_ ? bB[n] : bA[n];
                mma_f16(acc[0][n], U0.x, U1.x, U0.y, U1.y, B.x, B.y);
                if (m1) mma_f16(acc[1][n], U2.x, U3.x, U2.y, U3.y, B.x, B.y);
            }
#pragma unroll
            for (int n = 0; n < 4; n++) {   // refill consumed buffer (kk+2)
                if (half_)
                    bB[n] = g_W3H[(kk + 2) * 1024 + fslot + n * 32];
                else
                    bA[n] = g_W3H[(kk + 2) * 1024 + fslot + n * 32];
            }
        }
    }
    __syncthreads();                        // all h2 reads done (C overlay)

    // ---- store C (fp32) into cbuf ----
#pragma unroll
    for (int s = 0; s < 2; s++) {
        if (s == 0 || m1) {
#pragma unroll
            for (int n = 0; n < 4; n++) {
                const int col = ng * 32 + n * 8 + 2 * j;
                *(float2*)&cbuf[(s * 16 + arow) * CS + col] =
                    make_float2(acc[s][n][0], acc[s][n][1]);
                *(float2*)&cbuf[(s * 16 + arow + 8) * CS + col] =
                    make_float2(acc[s][n][2], acc[s][n][3]);
            }
        }
    }
    __syncthreads();

    // ---- epilogue: masked max over valid rows + b3 ----
    float m = -CUDART_INF_F;
    for (int p = 0; p < num; p++) m = fmaxf(m, cbuf[p * CS + t]);
    out[(size_t)v * 256 + t] = m + __ldg(&b3[t]);
}

// ---------------------------------------------------------------------------
// Launch. Inputs: Frustum_Voxel, Frustum_Voxel_num, W1,b1,W2,b2,W3,b3.
// Launch period 2 -> ncu -s 5 -c 1 lands on the main kernel.
// ---------------------------------------------------------------------------
extern "C" void kernel_launch(void* const* d_in, const int* in_sizes, int n_in,
                              void* d_out, int out_size) {
    const float* fv    = (const float*)d_in[0];
    const int*   fvnum = (const int*)  d_in[1];
    const float* W1    = (const float*)d_in[2];
    const float* b1    = (const float*)d_in[3];
    const float* W2    = (const float*)d_in[4];
    const float* b2    = (const float*)d_in[5];
    const float* W3    = (const float*)d_in[6];
    const float* b3    = (const float*)d_in[7];
    float* out = (float*)d_out;

    const int V = in_sizes[1];                  // 18432 voxels

    prep_kernel<<<73, 256>>>(W2, W3, b1, b2, b3);
    voxel_tc_kernel<<<V, NTHREADS>>>(fv, fvnum, W1, b1, b2, b3, out);
}